// round 3
// baseline (speedup 1.0000x reference)
#include <cuda_runtime.h>

// out[b][j] = sum over pixels (y,x) of image b with (y & x) == j, j in [0,1024).
//
// Decomposition: bin j = ((y>>5)&(x>>5))<<5 | ((y&31)&(x&31)).
// Each warp processes a 32-row x 128-col "supertile" (4 column-tiles of 32).
// Lane l loads float4 at cols 4l..4l+3:  x&3 = element index e (in-register),
// x bits 2..4 = lane bits 0..2 (m), x>>5 = 4*warp + (l>>3).
// Row index within tile (ylo) is a compile-time constant (full unroll), so the
// per-bit AND-reduction is: register adds for x bits 0-1, shfl_xor butterflies
// for x bits 2-4 (only where the y bit is 0), predicated accumulate into 4
// per-lane registers (lane m owns bins hi*32 + m*4 + p for m subset of y_hi3).
// End of supertile: 4 global atomicAdds per lane.

#define FULLMASK 0xffffffffu

__device__ __forceinline__ float shx(float v, int msk) {
    return __shfl_xor_sync(FULLMASK, v, msk);
}

template<int YLO>
__device__ __forceinline__ void proc_row(float4 v, int m,
                                         float& a0, float& a1, float& a2, float& a3) {
    constexpr int q  = YLO & 3;          // y bits 0,1
    constexpr int yh = (YLO >> 2) & 7;   // y bits 2,3,4
    float s0 = 0.f, s1 = 0.f, s2 = 0.f, s3 = 0.f;

    // Reduce x bits 0,1 in-register: s[p] = sum of v[e] with (e & q) == p.
    if constexpr (q == 0)      { s0 = (v.x + v.y) + (v.z + v.w); }
    else if constexpr (q == 1) { s0 = v.x + v.z;  s1 = v.y + v.w; }
    else if constexpr (q == 2) { s0 = v.x + v.y;  s2 = v.z + v.w; }
    else                       { s0 = v.x; s1 = v.y; s2 = v.z; s3 = v.w; }

    // Butterfly-reduce x bits 2..4 across lanes where the y bit is 0.
    if constexpr ((yh & 1) == 0) {
        s0 += shx(s0, 1);
        if constexpr (q & 1)  s1 += shx(s1, 1);
        if constexpr (q & 2)  s2 += shx(s2, 1);
        if constexpr (q == 3) s3 += shx(s3, 1);
    }
    if constexpr ((yh & 2) == 0) {
        s0 += shx(s0, 2);
        if constexpr (q & 1)  s1 += shx(s1, 2);
        if constexpr (q & 2)  s2 += shx(s2, 2);
        if constexpr (q == 3) s3 += shx(s3, 2);
    }
    if constexpr ((yh & 4) == 0) {
        s0 += shx(s0, 4);
        if constexpr (q & 1)  s1 += shx(s1, 4);
        if constexpr (q & 2)  s2 += shx(s2, 4);
        if constexpr (q == 3) s3 += shx(s3, 4);
    }

    // Lane m is the canonical owner iff m is a subset of yh.
    if ((m & ~yh & 7) == 0) {
        a0 += s0;
        if constexpr (q & 1)  a1 += s1;
        if constexpr (q & 2)  a2 += s2;
        if constexpr (q == 3) a3 += s3;
    }
}

template<int G>
__device__ __forceinline__ void do_group(const float* __restrict__ base, int lane, int m,
                                         float& a0, float& a1, float& a2, float& a3) {
    float4 vv[8];
    #pragma unroll
    for (int i = 0; i < 8; ++i)
        vv[i] = *reinterpret_cast<const float4*>(base + (size_t)(G * 8 + i) * 1024 + 4 * lane);
    proc_row<G*8+0>(vv[0], m, a0, a1, a2, a3);
    proc_row<G*8+1>(vv[1], m, a0, a1, a2, a3);
    proc_row<G*8+2>(vv[2], m, a0, a1, a2, a3);
    proc_row<G*8+3>(vv[3], m, a0, a1, a2, a3);
    proc_row<G*8+4>(vv[4], m, a0, a1, a2, a3);
    proc_row<G*8+5>(vv[5], m, a0, a1, a2, a3);
    proc_row<G*8+6>(vv[6], m, a0, a1, a2, a3);
    proc_row<G*8+7>(vv[7], m, a0, a1, a2, a3);
}

__global__ void __launch_bounds__(256) CNNDST_bin_kernel(
        const float* __restrict__ M, float* __restrict__ out) {
    const int blk  = blockIdx.x;       // 2048 blocks = 64 images * 32 row-tiles
    const int b    = blk >> 5;         // image
    const int r    = blk & 31;         // row-tile: rows [32r, 32r+32)
    const int w    = threadIdx.x >> 5; // warp 0..7 -> cols [128w, 128w+128)
    const int lane = threadIdx.x & 31;
    const int m    = lane & 7;

    const float* base = M + (size_t)b * (1024 * 1024) + (size_t)(r * 32) * 1024 + w * 128;

    float a0 = 0.f, a1 = 0.f, a2 = 0.f, a3 = 0.f;
    do_group<0>(base, lane, m, a0, a1, a2, a3);
    do_group<1>(base, lane, m, a0, a1, a2, a3);
    do_group<2>(base, lane, m, a0, a1, a2, a3);
    do_group<3>(base, lane, m, a0, a1, a2, a3);

    const int t  = lane >> 3;           // column-tile within supertile
    const int hi = r & (4 * w + t);     // high 5 bin bits
    float* o = out + ((size_t)b << 10) + (hi << 5) + (m << 2);
    atomicAdd(o + 0, a0);
    atomicAdd(o + 1, a1);
    atomicAdd(o + 2, a2);
    atomicAdd(o + 3, a3);
}

__global__ void CNNDST_zero_kernel(float* __restrict__ out) {
    out[(size_t)blockIdx.x * 1024 + threadIdx.x] = 0.f;
}

extern "C" void kernel_launch(void* const* d_in, const int* in_sizes, int n_in,
                              void* d_out, int out_size) {
    const float* M = (const float*)d_in[0];   // (64, 1, 1024, 1024) float32
    float* out = (float*)d_out;               // (64, 1024, 1, 1, 1) float32
    (void)in_sizes; (void)n_in; (void)out_size;

    CNNDST_zero_kernel<<<64, 1024>>>(out);
    CNNDST_bin_kernel<<<2048, 256>>>(M, out);
}